// round 11
// baseline (speedup 1.0000x reference)
#include <cuda_runtime.h>
#include <cstdint>

// PixelPrototypeDistanceLoss — B=8, D=256, H=W=128, C=19, IGNORE=19
// loss = mean over valid pixels of (1 - emb[b,:,h,w] . Q[lb]) ^ 2
//
// R11: TMA (cp.async.bulk) pipeline. R4-R10 post-mortem: EVERY LDG/LDGSTS
// structuring (depth x8, warps x2, double-buffer, cp.async) pinned at
// 4.1-4.5 TB/s -> the L1tex per-request path caps SM bytes-in-flight.
// TMA bulk copies use the TMA engine (chip cap ~ LTS ~6.9 TB/s), bypassing it.
//  - CTA = 512 contiguous px x full D; 3-stage ring, stage = 4 planes x 2KB
//    (one 2KB bulk op per plane, expect_tx 8KB/stage, single mbarrier/stage)
//  - 256 thr: (pg 0..127, h 0/1); h consumes planes {2h,2h+1} of each stage
//  - Q in SMEM stride 257 (conflict-free gather)
//  - fused last-block-done reduction (counter self-rearms; no spin-waits)
//
// lb is int32 on device (JAX x64 disabled).

constexpr int Bv = 8, Dv = 256, Hv = 128, Wv = 128, Cv = 19, IGNORE = 19;
constexpr int HW = Hv * Wv;                     // 16384
constexpr long long NPIX = (long long)Bv * HW;  // 131072
constexpr int THREADS = 256;
constexpr int PG = 128;                         // float4 groups per CTA (512 px)
constexpr int NBLOCKS = (int)(NPIX / (4 * PG)); // 256
constexpr int QSTRIDE = Dv + 1;                 // 257
constexpr int PPS = 4;                          // planes per stage
constexpr int STAGES = 3;
constexpr int NCH = Dv / PPS;                   // 64 chunks
constexpr int PLANE_BYTES = PG * 16;            // 2048
constexpr int STAGE_BYTES = PPS * PLANE_BYTES;  // 8192

__device__ float g_bsum[NBLOCKS];
__device__ float g_bcnt[NBLOCKS];
__device__ unsigned int g_count = 0;            // rearmed by last block each launch

__device__ __forceinline__ uint32_t smem_u32(const void* p) {
    return (uint32_t)__cvta_generic_to_shared(p);
}
__device__ __forceinline__ void mbar_init(uint32_t mbar, uint32_t cnt) {
    asm volatile("mbarrier.init.shared.b64 [%0], %1;" :: "r"(mbar), "r"(cnt) : "memory");
}
__device__ __forceinline__ void mbar_expect_tx(uint32_t mbar, uint32_t bytes) {
    asm volatile("mbarrier.arrive.expect_tx.shared.b64 _, [%0], %1;"
                 :: "r"(mbar), "r"(bytes) : "memory");
}
__device__ __forceinline__ void mbar_wait(uint32_t mbar, uint32_t parity) {
    uint32_t done;
    asm volatile(
        "{\n\t.reg .pred p;\n\t"
        "mbarrier.try_wait.parity.acquire.cta.shared::cta.b64 p, [%1], %2;\n\t"
        "selp.b32 %0, 1, 0, p;\n\t}"
        : "=r"(done) : "r"(mbar), "r"(parity) : "memory");
    if (!done) {
        asm volatile(
            "{\n\t.reg .pred P1;\n\t"
            "W_%=:\n\t"
            "mbarrier.try_wait.parity.acquire.cta.shared::cta.b64 P1, [%0], %1, 0x989680;\n\t"
            "@P1 bra.uni D_%=;\n\t"
            "bra.uni W_%=;\n\t"
            "D_%=:\n\t}"
            :: "r"(mbar), "r"(parity) : "memory");
    }
}
__device__ __forceinline__ void tma_bulk_1d(uint32_t dst_smem, const void* src,
                                            uint32_t bytes, uint32_t mbar) {
    asm volatile(
        "cp.async.bulk.shared::cta.global.mbarrier::complete_tx::bytes [%0], [%1], %2, [%3];"
        :: "r"(dst_smem), "l"(src), "r"(bytes), "r"(mbar) : "memory");
}
__device__ __forceinline__ void fence_proxy_async_shared() {
    asm volatile("fence.proxy.async.shared::cta;" ::: "memory");
}

__global__ void __launch_bounds__(THREADS, 4)
ppd_fused(const float* __restrict__ emb,
          const int4* __restrict__ lb4,
          const float* __restrict__ Q,
          float* __restrict__ out) {
    __shared__ float4 ring[STAGES][PPS][PG];        // 24 KB
    __shared__ float Qs[Cv * QSTRIDE];              // ~19.5 KB
    __shared__ float s_part[PG * 4];                // 2 KB
    __shared__ float s_sq[4];
    __shared__ float s_ct[4];
    __shared__ double sh_s[8];
    __shared__ double sh_k[8];
    __shared__ alignas(8) unsigned long long mbar_sto[STAGES];
    __shared__ int s_last;

    const int tid = threadIdx.x;
    const int pg  = tid & (PG - 1);             // 0..127
    const int h   = tid >> 7;                   // d-parity half 0/1

    const uint32_t mb0 = smem_u32(&mbar_sto[0]);

    // mbarrier init (every launch; graph-replay safe: no pending ops at entry)
    if (tid == 0) {
#pragma unroll
        for (int s = 0; s < STAGES; ++s) mbar_init(mb0 + 8u * s, 1u);
        fence_proxy_async_shared();
    }
    __syncthreads();

    const int b      = blockIdx.x >> 5;         // 32 CTAs per image
    const int pxbase = (blockIdx.x & 31) * (PG * 4);   // 512 px per CTA
    const float* gbase = emb + (long long)b * Dv * HW + pxbase;

    // prologue: issue chunks 0,1 into stages 0,1
    if (tid == 0) {
#pragma unroll
        for (int s = 0; s < 2; ++s) {
            mbar_expect_tx(mb0 + 8u * s, STAGE_BYTES);
#pragma unroll
            for (int p = 0; p < PPS; ++p)
                tma_bulk_1d(smem_u32(&ring[s][p][0]),
                            gbase + (long long)(s * PPS + p) * HW,
                            PLANE_BYTES, mb0 + 8u * s);
        }
    }

    // labels + Q staging (overlaps prologue TMA)
    const int t4 = blockIdx.x * PG + pg;
    const int4 lbv = lb4[t4];
    const bool v0 = lbv.x != IGNORE, v1 = lbv.y != IGNORE,
               v2 = lbv.z != IGNORE, v3 = lbv.w != IGNORE;

    for (int i = tid; i < Cv * Dv; i += THREADS) {
        const int cc = i >> 8;
        const int dd = i & (Dv - 1);
        Qs[cc * QSTRIDE + dd] = Q[i];
    }
    __syncthreads();

    const float* q0 = &Qs[(v0 ? lbv.x : 0) * QSTRIDE];
    const float* q1 = &Qs[(v1 ? lbv.y : 0) * QSTRIDE];
    const float* q2 = &Qs[(v2 ? lbv.z : 0) * QSTRIDE];
    const float* q3 = &Qs[(v3 ? lbv.w : 0) * QSTRIDE];

    float a0 = 0.f, a1 = 0.f, a2 = 0.f, a3 = 0.f;

    for (int c = 0; c < NCH; ++c) {
        const int s = c % STAGES;

        // issue chunk c+2 into stage (c+2)%3 (that stage was consumed at c-1)
        if (tid == 0 && c + 2 < NCH) {
            const int s2 = (c + 2) % STAGES;
            mbar_expect_tx(mb0 + 8u * s2, STAGE_BYTES);
#pragma unroll
            for (int p = 0; p < PPS; ++p)
                tma_bulk_1d(smem_u32(&ring[s2][p][0]),
                            gbase + (long long)((c + 2) * PPS + p) * HW,
                            PLANE_BYTES, mb0 + 8u * s2);
        }

        // wait for chunk c (stage s, fill #c/3 -> parity (c/3)&1)
        mbar_wait(mb0 + 8u * s, (uint32_t)((c / STAGES) & 1));

        // consume: this thread's 2 planes of the stage
#pragma unroll
        for (int pl = 0; pl < 2; ++pl) {
            const int p = 2 * h + pl;
            const float4 v = ring[s][p][pg];
            const int d = c * PPS + p;
            a0 = fmaf(v.x, q0[d], a0);
            a1 = fmaf(v.y, q1[d], a1);
            a2 = fmaf(v.z, q2[d], a2);
            a3 = fmaf(v.w, q3[d], a3);
        }
        __syncthreads();                         // stage s free before reissue
    }

    // combine d-halves
    if (h == 1) {
        s_part[pg * 4 + 0] = a0;
        s_part[pg * 4 + 1] = a1;
        s_part[pg * 4 + 2] = a2;
        s_part[pg * 4 + 3] = a3;
    }
    __syncthreads();

    const int wid  = tid >> 5;
    const int lane = tid & 31;

    if (h == 0) {                               // warps 0-3 finish the loss
        a0 += s_part[pg * 4 + 0];
        a1 += s_part[pg * 4 + 1];
        a2 += s_part[pg * 4 + 2];
        a3 += s_part[pg * 4 + 3];

        const float r0 = 1.f - a0, r1 = 1.f - a1, r2 = 1.f - a2, r3 = 1.f - a3;
        float sq  = (v0 ? r0 * r0 : 0.f) + (v1 ? r1 * r1 : 0.f)
                  + (v2 ? r2 * r2 : 0.f) + (v3 ? r3 * r3 : 0.f);
        float cnt = (float)v0 + (float)v1 + (float)v2 + (float)v3;

#pragma unroll
        for (int o = 16; o > 0; o >>= 1) {
            sq  += __shfl_down_sync(0xFFFFFFFFu, sq,  o);
            cnt += __shfl_down_sync(0xFFFFFFFFu, cnt, o);
        }
        if (lane == 0) { s_sq[wid] = sq; s_ct[wid] = cnt; }
    }
    __syncthreads();

    if (tid == 0) {
        g_bsum[blockIdx.x] = s_sq[0] + s_sq[1] + s_sq[2] + s_sq[3];
        g_bcnt[blockIdx.x] = s_ct[0] + s_ct[1] + s_ct[2] + s_ct[3];
        __threadfence();
        const unsigned prev = atomicAdd(&g_count, 1u);
        s_last = (prev == (unsigned)(NBLOCKS - 1));
    }
    __syncthreads();

    if (s_last) {                               // last block reduces 256 partials
        double a = 0.0, k = 0.0;
        for (int i = tid; i < NBLOCKS; i += THREADS) {
            a += (double)__ldcg(&g_bsum[i]);
            k += (double)__ldcg(&g_bcnt[i]);
        }
#pragma unroll
        for (int o = 16; o > 0; o >>= 1) {
            a += __shfl_down_sync(0xFFFFFFFFu, a, o);
            k += __shfl_down_sync(0xFFFFFFFFu, k, o);
        }
        if (lane == 0) { sh_s[wid] = a; sh_k[wid] = k; }
        __syncthreads();
        if (wid == 0) {
            double aa = (lane < 8) ? sh_s[lane] : 0.0;
            double kk = (lane < 8) ? sh_k[lane] : 0.0;
#pragma unroll
            for (int o = 4; o > 0; o >>= 1) {
                aa += __shfl_down_sync(0xFFFFFFFFu, aa, o);
                kk += __shfl_down_sync(0xFFFFFFFFu, kk, o);
            }
            if (lane == 0) {
                out[0] = (float)(aa / kk);
                g_count = 0;                    // rearm for next replay
            }
        }
    }
}

extern "C" void kernel_launch(void* const* d_in, const int* in_sizes, int n_in,
                              void* d_out, int out_size) {
    const float* emb = (const float*)d_in[0];   // [8,256,128,128] f32
    const int4*  lb  = (const int4*)d_in[1];    // [8,128,128] i32
    const float* Q   = (const float*)d_in[2];   // [19,256] f32
    float*       out = (float*)d_out;           // scalar f32

    (void)in_sizes; (void)n_in; (void)out_size;

    ppd_fused<<<NBLOCKS, THREADS>>>(emb, lb, Q, out);
}

// round 14
// speedup vs baseline: 1.4865x; 1.4865x over previous
#include <cuda_runtime.h>

// PixelPrototypeDistanceLoss — B=8, D=256, H=W=128, C=19, IGNORE=19
// loss = mean over valid pixels of (1 - emb[b,:,h,w] . Q[lb]) ^ 2
//
// R14 == R12/R13 resubmitted verbatim (neither ran: broker infra failures;
// precedent R5/R6->R7 shows consecutive broker failures are content-independent).
// R12 = R9 (best, 29.9us) + prefetch.global.L2 one chunk ahead of the LDG point.
// R4-R11 post-mortem: six load structurings all pinned at 3.8-4.5 TB/s ->
// per-SM L1tex response queue (~248 line slots) caps in-flight lines; every
// demand request holds a slot for the full ~577-cyc DRAM latency.
// Fix: untracked L2 prefetch stream drives DRAM; demand LDGs then hit L2
// (~240 cyc) -> 2.4x shorter slot residency -> ~2x demand BW ceiling.
//
// lb is int32 on device (JAX x64 disabled).

constexpr int Bv = 8, Dv = 256, Hv = 128, Wv = 128, Cv = 19, IGNORE = 19;
constexpr int HW = Hv * Wv;                     // 16384
constexpr long long NPIX = (long long)Bv * HW;  // 131072
constexpr int THREADS = 256;                    // 128 pixel-groups x 2 d-halves
constexpr int PG_PER_BLOCK = 128;               // float4 groups (512 px) per block
constexpr int NBLOCKS = (int)(NPIX / (4 * PG_PER_BLOCK));  // 256
constexpr int QSTRIDE = Dv + 1;                 // 257
constexpr int NB = 8;                           // pipeline buffer depth
constexpr int DHALF = Dv / 2;                   // 128 d per half
constexpr int HW4 = HW / 4;                     // float4 stride per d
constexpr int NCHUNK = DHALF / (2 * NB);        // 8 double-chunks

__device__ float g_bsum[NBLOCKS];
__device__ float g_bcnt[NBLOCKS];
__device__ unsigned int g_count = 0;            // rearmed by last block each launch

__device__ __forceinline__ void prefetch_l2(const void* p) {
    asm volatile("prefetch.global.L2 [%0];" :: "l"(p));
}

__global__ void __launch_bounds__(THREADS, 2)
ppd_fused(const float4* __restrict__ emb4,
          const int4* __restrict__ lb4,
          const float* __restrict__ Q,
          float* __restrict__ out) {
    __shared__ float Qs[Cv * QSTRIDE];          // ~19.5 KB
    __shared__ float s_part[PG_PER_BLOCK * 4];  // 2 KB upper-half partials
    __shared__ float s_sq[4];
    __shared__ float s_ct[4];
    __shared__ double sh_s[8];
    __shared__ double sh_k[8];
    __shared__ int s_last;

    const int tid  = threadIdx.x;
    const int pg   = tid & (PG_PER_BLOCK - 1);  // pixel-group 0..127
    const int half = tid >> 7;                  // d-half 0/1

    const int t4 = blockIdx.x * PG_PER_BLOCK + pg;
    const int n0 = t4 * 4;

    const int4 lbv = lb4[t4];
    const bool v0 = lbv.x != IGNORE, v1 = lbv.y != IGNORE,
               v2 = lbv.z != IGNORE, v3 = lbv.w != IGNORE;

    for (int i = tid; i < Cv * Dv; i += THREADS) {
        const int cc = i >> 8;
        const int dd = i & (Dv - 1);
        Qs[cc * QSTRIDE + dd] = Q[i];
    }
    __syncthreads();

    const float* q0 = &Qs[(v0 ? lbv.x : 0) * QSTRIDE];
    const float* q1 = &Qs[(v1 ? lbv.y : 0) * QSTRIDE];
    const float* q2 = &Qs[(v2 ? lbv.z : 0) * QSTRIDE];
    const float* q3 = &Qs[(v3 ? lbv.w : 0) * QSTRIDE];

    const int b  = n0 >> 14;
    const int hw = n0 & (HW - 1);
    const int dbase = half * DHALF;
    const float4* ep = emb4 + ((long long)b * Dv * HW + hw) / 4
                            + (long long)dbase * HW4;

    float a0 = 0.f, a1 = 0.f, a2 = 0.f, a3 = 0.f;

    float4 va[NB], vb[NB];
    // warm L2 for chunk 1's planes (16..31) before its LDGs fire next iteration
#pragma unroll
    for (int j = 0; j < 2 * NB; ++j)
        prefetch_l2(ep + (long long)(2 * NB + j) * HW4);

    // prologue: fill A with d 0..7
#pragma unroll
    for (int j = 0; j < NB; ++j)
        va[j] = __ldcs(ep + (long long)j * HW4);

#pragma unroll
    for (int c2 = 0; c2 < NCHUNK; ++c2) {
        const int dA = c2 * 2 * NB;             // A holds dA..dA+7

        // L2-prefetch chunk c2+2 (its LDGs issue during iteration c2+1):
        // lead ~1 iteration (~600-800 cyc) >= DRAM latency; untracked stream.
        if (c2 + 2 < NCHUNK) {
#pragma unroll
            for (int j = 0; j < 2 * NB; ++j)
                prefetch_l2(ep + (long long)((c2 + 2) * 2 * NB + j) * HW4);
        }

        // prefetch B: dA+8..dA+15
#pragma unroll
        for (int j = 0; j < NB; ++j)
            vb[j] = __ldcs(ep + (long long)(dA + NB + j) * HW4);

        // consume A (B in flight)
#pragma unroll
        for (int j = 0; j < NB; ++j) {
            const int d = dbase + dA + j;
            a0 = fmaf(va[j].x, q0[d], a0);
            a1 = fmaf(va[j].y, q1[d], a1);
            a2 = fmaf(va[j].z, q2[d], a2);
            a3 = fmaf(va[j].w, q3[d], a3);
        }

        // prefetch A for next chunk: dA+16..dA+23
        if (c2 + 1 < NCHUNK) {
#pragma unroll
            for (int j = 0; j < NB; ++j)
                va[j] = __ldcs(ep + (long long)(dA + 2 * NB + j) * HW4);
        }

        // consume B (next A in flight)
#pragma unroll
        for (int j = 0; j < NB; ++j) {
            const int d = dbase + dA + NB + j;
            a0 = fmaf(vb[j].x, q0[d], a0);
            a1 = fmaf(vb[j].y, q1[d], a1);
            a2 = fmaf(vb[j].z, q2[d], a2);
            a3 = fmaf(vb[j].w, q3[d], a3);
        }
    }

    if (half == 1) {
        s_part[pg * 4 + 0] = a0;
        s_part[pg * 4 + 1] = a1;
        s_part[pg * 4 + 2] = a2;
        s_part[pg * 4 + 3] = a3;
    }
    __syncthreads();

    const int wid  = tid >> 5;
    const int lane = tid & 31;

    if (half == 0) {
        a0 += s_part[pg * 4 + 0];
        a1 += s_part[pg * 4 + 1];
        a2 += s_part[pg * 4 + 2];
        a3 += s_part[pg * 4 + 3];

        const float r0 = 1.f - a0, r1 = 1.f - a1, r2 = 1.f - a2, r3 = 1.f - a3;
        float sq  = (v0 ? r0 * r0 : 0.f) + (v1 ? r1 * r1 : 0.f)
                  + (v2 ? r2 * r2 : 0.f) + (v3 ? r3 * r3 : 0.f);
        float cnt = (float)v0 + (float)v1 + (float)v2 + (float)v3;

#pragma unroll
        for (int o = 16; o > 0; o >>= 1) {
            sq  += __shfl_down_sync(0xFFFFFFFFu, sq,  o);
            cnt += __shfl_down_sync(0xFFFFFFFFu, cnt, o);
        }
        if (lane == 0) { s_sq[wid] = sq; s_ct[wid] = cnt; }
    }
    __syncthreads();

    if (tid == 0) {
        float s = 0.f, k = 0.f;
#pragma unroll
        for (int w = 0; w < 4; ++w) { s += s_sq[w]; k += s_ct[w]; }
        g_bsum[blockIdx.x] = s;
        g_bcnt[blockIdx.x] = k;
        __threadfence();
        const unsigned prev = atomicAdd(&g_count, 1u);
        s_last = (prev == (unsigned)(NBLOCKS - 1));
    }
    __syncthreads();

    if (s_last) {
        double a = 0.0, k = 0.0;
        for (int i = tid; i < NBLOCKS; i += THREADS) {
            a += (double)__ldcg(&g_bsum[i]);
            k += (double)__ldcg(&g_bcnt[i]);
        }
#pragma unroll
        for (int o = 16; o > 0; o >>= 1) {
            a += __shfl_down_sync(0xFFFFFFFFu, a, o);
            k += __shfl_down_sync(0xFFFFFFFFu, k, o);
        }
        if (lane == 0) { sh_s[wid] = a; sh_k[wid] = k; }
        __syncthreads();
        if (wid == 0) {
            double aa = (lane < THREADS / 32) ? sh_s[lane] : 0.0;
            double kk = (lane < THREADS / 32) ? sh_k[lane] : 0.0;
#pragma unroll
            for (int o = 4; o > 0; o >>= 1) {
                aa += __shfl_down_sync(0xFFFFFFFFu, aa, o);
                kk += __shfl_down_sync(0xFFFFFFFFu, kk, o);
            }
            if (lane == 0) {
                out[0] = (float)(aa / kk);
                g_count = 0;
            }
        }
    }
}

extern "C" void kernel_launch(void* const* d_in, const int* in_sizes, int n_in,
                              void* d_out, int out_size) {
    const float4* emb = (const float4*)d_in[0]; // [8,256,128,128] f32
    const int4*   lb  = (const int4*)d_in[1];   // [8,128,128] i32
    const float*  Q   = (const float*)d_in[2];  // [19,256] f32
    float*        out = (float*)d_out;          // scalar f32

    (void)in_sizes; (void)n_in; (void)out_size;

    ppd_fused<<<NBLOCKS, THREADS>>>(emb, lb, Q, out);
}